// round 16
// baseline (speedup 1.0000x reference)
#include <cuda_runtime.h>
#include <cstdint>

#define BB 32
#define AA 8400
#define AA_PAD 8448
#define NCLS 80
#define KTOP 1024
#define GG 32
#define NSUP 16
#define MAX_DET 300
#define KW (KTOP/32)
#define NBIN2 4098           // bin0 = conf==0, bins 1..4097 = (cbits>>12) - 0x3E800 + 1
#define NBIN2_PAD 4112
#define CAND 2048

typedef unsigned long long u64;

// ---------------- static device scratch ----------------
__device__ u64 d_keys[BB * AA];
__device__ int d_hist[BB * NBIN2_PAD];   // zero-init; fused kernel re-zeroes after use

__device__ __forceinline__ unsigned f2sortable(float f) {
    unsigned b = __float_as_uint(f);
    return (b & 0x80000000u) ? ~b : (b | 0x80000000u);
}
__device__ __forceinline__ float sortable2f(unsigned s) {
    return __uint_as_float((s & 0x80000000u) ? (s ^ 0x80000000u) : ~s);
}

// ---------------- 1. decode: 4 threads per quad (20 classes each) ----------------
// key = (conf_bits << 32) | ((AA-1-a) << 7) | cls   (cls below index: tie order intact)
// Out-of-range threads clamp onto the last quad so EVERY lane executes the shfl
// collectives; only stores are guarded.
__global__ void decode_kernel(const float* __restrict__ preds) {
    __shared__ int hh[NBIN2];
    int b = blockIdx.y;
    int t = blockIdx.x * blockDim.x + threadIdx.x;   // 0 .. 8447
    for (int i = threadIdx.x; i < NBIN2; i += blockDim.x) hh[i] = 0;
    __syncthreads();

    bool live = (t < AA);
    int q = live ? (t >> 2) : (AA / 4 - 1);
    int k = t & 3;
    const float4* p4 = (const float4*)(preds + (size_t)b * 84 * AA);
    const int QW = AA / 4;                           // 2100

    float4 best = p4[(4 + k) * QW + q];
    int c0 = k, c1 = k, c2 = k, c3 = k;
    #pragma unroll 5
    for (int i = 1; i < 20; i++) {
        int c = k + 4 * i;
        float4 v = p4[(4 + c) * QW + q];
        if (v.x > best.x) { best.x = v.x; c0 = c; }
        if (v.y > best.y) { best.y = v.y; c1 = c; }
        if (v.z > best.z) { best.z = v.z; c2 = c; }
        if (v.w > best.w) { best.w = v.w; c3 = c; }
    }
    #pragma unroll
    for (int d = 1; d <= 2; d <<= 1) {
        float ox = __shfl_xor_sync(0xffffffffu, best.x, d);
        float oy = __shfl_xor_sync(0xffffffffu, best.y, d);
        float oz = __shfl_xor_sync(0xffffffffu, best.z, d);
        float ow = __shfl_xor_sync(0xffffffffu, best.w, d);
        int   o0 = __shfl_xor_sync(0xffffffffu, c0, d);
        int   o1 = __shfl_xor_sync(0xffffffffu, c1, d);
        int   o2 = __shfl_xor_sync(0xffffffffu, c2, d);
        int   o3 = __shfl_xor_sync(0xffffffffu, c3, d);
        if (ox > best.x || (ox == best.x && o0 < c0)) { best.x = ox; c0 = o0; }
        if (oy > best.y || (oy == best.y && o1 < c1)) { best.y = oy; c1 = o1; }
        if (oz > best.z || (oz == best.z && o2 < c2)) { best.z = oz; c2 = o2; }
        if (ow > best.w || (ow == best.w && o3 < c3)) { best.w = ow; c3 = o3; }
    }
    if (live) {
        float bv = (k == 0) ? best.x : (k == 1) ? best.y : (k == 2) ? best.z : best.w;
        int   cv = (k == 0) ? c0     : (k == 1) ? c1     : (k == 2) ? c2     : c3;
        int a = q * 4 + k;
        float conf = (bv > 0.25f) ? bv : 0.0f;
        unsigned cbits = __float_as_uint(conf);
        d_keys[b * AA + a] = ((u64)cbits << 32) | ((unsigned)(AA - 1 - a) << 7)
                           | (unsigned)cv;
        int bin = (conf == 0.0f) ? 0 : (int)(cbits >> 12) - 0x3E800 + 1;
        atomicAdd(&hh[bin], 1);
    }
    __syncthreads();
    for (int i = threadIdx.x; i < NBIN2; i += blockDim.x)
        if (hh[i]) atomicAdd(&d_hist[b * NBIN2_PAD + i], hh[i]);
}

// ---------------- dynamic smem layout (bytes); regions are overlaid by phase ----------------
#define OFF_CANDS  0        // u64[2048] 16384  -> after rank: s_box float4[1024]
#define OFF_SBOX   16384    // float4[1024] shifted boxes        16384
#define OFF_HIST   32768    // int[4098] 16400 -> after cutoff: s_conf/s_cls/s_pv
#define OFF_CONF   32768    //   float[1024] 4096
#define OFF_CLS    36864    //   int[1024]   4096
#define OFF_PV     40960    //   uint[32]     128
#define OFF_CMASK  49168    // uint[80*32] 10240
#define OFF_KEEP   59408    // uint[32] 128
#define FUSED_SMEM 59536

// ---------------- 2. fused: select(rank-by-count) -> NMS -> trim -> match -> stats ----------------
#define BINS_PER_T 5
__global__ void __launch_bounds__(1024) fused_kernel(
    const float* __restrict__ preds,
    const float* __restrict__ gt_boxes,
    const int*   __restrict__ gt_cls,
    const int*   __restrict__ gt_mask,
    const int*   __restrict__ cat_to_super,
    float* __restrict__ out)
{
    extern __shared__ unsigned char smraw[];
    u64*      s_cand  = (u64*)     (smraw + OFF_CANDS);
    float4*   s_box   = (float4*)  (smraw + OFF_CANDS);  // overlay after rank
    float4*   s_sbox  = (float4*)  (smraw + OFF_SBOX);
    int*      s_hist  = (int*)     (smraw + OFF_HIST);
    float*    s_conf  = (float*)   (smraw + OFF_CONF);   // overlay after cutoff
    int*      s_cls   = (int*)     (smraw + OFF_CLS);
    unsigned* s_pv    = (unsigned*)(smraw + OFF_PV);
    unsigned* s_cmask = (unsigned*)(smraw + OFF_CMASK);
    unsigned* s_keep  = (unsigned*)(smraw + OFF_KEEP);

    __shared__ float4 sgt[GG];
    __shared__ int    sgc[GG];
    __shared__ u64    sbest[GG];
    __shared__ unsigned s_keepw[KW];
    __shared__ int s_wsum[32], s_wafter[32];
    __shared__ int sh_cstar, sh_scnt, sh_npred;
    __shared__ u64 sh_thr;

    int b    = blockIdx.x;
    int tid  = threadIdx.x;                 // 1024
    int lane = tid & 31;
    int wid  = tid >> 5;
    const u64* keys = d_keys + (size_t)b * AA;

    // ---- stage hist (and re-zero global for next launch) ----
    for (int i = tid; i < NBIN2; i += 1024) {
        s_hist[i] = d_hist[b * NBIN2_PAD + i];
        d_hist[b * NBIN2_PAD + i] = 0;
    }
    for (int i = tid; i < NCLS * 32; i += 1024) s_cmask[i] = 0;
    if (tid < 32) s_keep[tid] = 0;
    if (tid < GG) {
        const float* gb = gt_boxes + (size_t)(b * GG + tid) * 4;
        sgt[tid] = make_float4(gb[0], gb[1], gb[2], gb[3]);
        sgc[tid] = gt_cls[b * GG + tid];
        sbest[tid] = 0ull;
    }
    if (tid == 0) { sh_cstar = 1; sh_scnt = 0; sh_npred = 0; }
    __syncthreads();

    // ---- hierarchical suffix scan over bins 1..4097 -> cutoff bin (2 barriers) ----
    {
        int partial = 0;
        #pragma unroll
        for (int k = 0; k < BINS_PER_T; k++) {
            int c = tid * BINS_PER_T + k;
            if (c >= 1 && c < NBIN2) partial += s_hist[c];
        }
        // warp-internal suffix sum (sum of partials from this lane to lane 31)
        int wsfx = partial;
        #pragma unroll
        for (int d = 1; d < 32; d <<= 1) {
            int v = __shfl_down_sync(0xffffffffu, wsfx, d);
            if (lane + d < 32) wsfx += v;
        }
        if (lane == 0) s_wsum[wid] = wsfx;   // warp total
        __syncthreads();
        if (wid == 0) {
            int wt = s_wsum[lane];
            int wsf = wt;
            #pragma unroll
            for (int d = 1; d < 32; d <<= 1) {
                int v = __shfl_down_sync(0xffffffffu, wsf, d);
                if (lane + d < 32) wsf += v;
            }
            // suffix of warps strictly after lane
            s_wafter[lane] = wsf - wt;
        }
        __syncthreads();
        int sfx = wsfx + s_wafter[wid];      // sum of partials from THIS thread onward
        int nxt = sfx - partial;             // sum from next thread onward
        if (sfx >= KTOP && nxt < KTOP) {     // unique firing thread
            int cum = nxt, cstar = 1;
            for (int c = min(tid * BINS_PER_T + BINS_PER_T - 1, NBIN2 - 1);
                 c >= tid * BINS_PER_T; c--) {
                if (c < 1) break;
                cum += s_hist[c];
                if (cum >= KTOP) { cstar = c; break; }
            }
            sh_cstar = cstar;
        }
    }
    __syncthreads();
    if (tid == 0) {
        unsigned thrhi = ((unsigned)(sh_cstar - 1 + 0x3E800)) << 12;
        sh_thr = (u64)thrhi << 32;
    }
    for (int i = tid; i < CAND; i += 1024) s_cand[i] = 0ull;
    __syncthreads();

    // ---- compact candidates >= thr (warp-aggregated) ----
    {
        u64 thr = sh_thr;
        for (int base = 0; base < AA_PAD; base += 1024) {
            int i = base + tid;
            u64 k = (i < AA) ? keys[i] : 0ull;
            bool pred = (i < AA) && (k >= thr);
            unsigned ball = __ballot_sync(0xffffffffu, pred);
            int cnt = __popc(ball);
            int pos0 = 0;
            if (lane == 0 && cnt) pos0 = atomicAdd(&sh_scnt, cnt);
            pos0 = __shfl_sync(0xffffffffu, pos0, 0);
            if (pred) {
                int pos = pos0 + __popc(ball & ((1u << lane) - 1));
                if (pos < CAND) s_cand[pos] = k;
            }
        }
    }
    __syncthreads();

    // ---- rank-by-count (keys unique -> exact permutation; no sort) ----
    int n = min(sh_scnt, CAND);
    u64 my0 = s_cand[tid];
    u64 my1 = s_cand[tid + 1024];
    int r0 = 0, r1 = 0;
    for (int j = 0; j < n; j++) {
        u64 kj = s_cand[j];                  // broadcast LDS
        r0 += (kj > my0);
        r1 += (kj > my1);
    }
    __syncthreads();                         // all s_cand reads done; s_box overlay safe

    // ---- scatter-gather: candidate -> rank slot ----
    {
        const float* p = preds + (size_t)b * 84 * AA;
        #pragma unroll
        for (int u = 0; u < 2; u++) {
            int idx  = tid + u * 1024;
            u64 key  = u ? my1 : my0;
            int rank = u ? r1 : r0;
            if (idx < n && rank < KTOP) {
                float conf = __uint_as_float((unsigned)(key >> 32));
                int a = AA - 1 - (int)((key >> 7) & 0x3FFF);
                int cls = (int)(key & 0x7F);
                float cx = p[0 * AA + a], cy = p[1 * AA + a];
                float w  = p[2 * AA + a], h  = p[3 * AA + a];
                float x1 = cx - 0.5f * w, y1 = cy - 0.5f * h;
                float x2 = cx + 0.5f * w, y2 = cy + 0.5f * h;
                float sh = (float)cls * 7680.0f;
                s_box[rank]  = make_float4(x1, y1, x2, y2);
                s_sbox[rank] = make_float4(x1 + sh, y1 + sh, x2 + sh, y2 + sh);
                s_conf[rank] = conf;
                s_cls[rank]  = cls;
                if (conf > 0.0f)
                    atomicOr(&s_cmask[cls * 32 + (rank >> 5)], 1u << (rank & 31));
            }
        }
    }
    __syncthreads();

    // ---- NMS: per-class warp greedy chains (cross-class IOU exactly zero) ----
    for (int c = wid; c < NCLS; c += 32) {
        unsigned rem_w = s_cmask[c * 32 + lane];
        unsigned keep_bits = 0;
        while (true) {
            unsigned anyb = __ballot_sync(0xffffffffu, rem_w != 0);
            if (!anyb) break;
            int src = __ffs(anyb) - 1;
            unsigned w0 = __shfl_sync(0xffffffffu, rem_w, src);
            int jb0 = __ffs(w0) - 1;
            int r = src * 32 + jb0;             // lowest remaining rank: KEPT
            if (lane == src) {
                rem_w &= ~(1u << jb0);
                keep_bits |= (1u << jb0);
            }
            float4 bi = s_sbox[r];
            float ai = (bi.z - bi.x) * (bi.w - bi.y);
            unsigned w = rem_w;
            while (w) {
                int jb = __ffs(w) - 1; w &= w - 1;
                float4 bj = s_sbox[lane * 32 + jb];
                float lx = fmaxf(bi.x, bj.x), ly = fmaxf(bi.y, bj.y);
                float rx = fminf(bi.z, bj.z), ry = fminf(bi.w, bj.w);
                float iw = fmaxf(rx - lx, 0.0f), ih = fmaxf(ry - ly, 0.0f);
                float inter = iw * ih;
                float aj = (bj.z - bj.x) * (bj.w - bj.y);
                float denom = ai + aj - inter + 1e-9f;
                float iou = __fdiv_rn(inter, denom);
                if (iou > 0.45f) rem_w &= ~(1u << jb);
            }
        }
        if (keep_bits) atomicOr(&s_keep[lane], keep_bits);
    }
    __syncthreads();

    // ---- MAX_DET trim in kept-rank order (warp 0) ----
    if (tid < 32) {
        unsigned keep_local = s_keep[lane];
        int myc = __popc(keep_local);
        int pre = myc;
        #pragma unroll
        for (int d = 1; d < 32; d <<= 1) {
            int v = __shfl_up_sync(0xffffffffu, pre, d);
            if (lane >= d) pre += v;
        }
        pre -= myc;
        unsigned kw2 = 0, tmp = keep_local;
        while (tmp) {
            int p = __ffs(tmp) - 1; tmp &= tmp - 1;
            int rank = pre + __popc(keep_local & ((1u << p) - 1));
            if (rank < MAX_DET) kw2 |= (1u << p);
        }
        s_keepw[lane] = kw2;
    }
    __syncthreads();

    // ---- pv bits + npred ----
    {
        bool kb = (s_keepw[tid >> 5] >> (tid & 31)) & 1u;
        bool pv = kb && (s_conf[tid] > 0.5f);
        unsigned ball = __ballot_sync(0xffffffffu, pv);
        if (lane == 0) {
            s_pv[wid] = ball;
            atomicAdd(&sh_npred, __popc(ball));
        }
    }
    __syncthreads();

    // ---- match: warp g owns GT g; one reduce per warp ----
    {
        int g = wid;
        float4 gb = sgt[g];
        int gc = sgc[g];
        float ag = (gb.z - gb.x) * (gb.w - gb.y);
        u64 best = 0ull;
        #pragma unroll 4
        for (int i = lane; i < KTOP; i += 32) {
            float4 bx = s_box[i];
            float lx = fmaxf(bx.x, gb.x), ly = fmaxf(bx.y, gb.y);
            float rx = fminf(bx.z, gb.z), ry = fminf(bx.w, gb.w);
            float iw = fmaxf(rx - lx, 0.0f), ih = fmaxf(ry - ly, 0.0f);
            float inter = iw * ih;
            float ap = (bx.z - bx.x) * (bx.w - bx.y);
            float iou = __fdiv_rn(inter, ap + ag - inter + 1e-9f);
            bool pv = (s_pv[i >> 5] >> (i & 31)) & 1u;
            float ioum = (pv && s_cls[i] == gc) ? iou : -1.0f;
            u64 key = ((u64)f2sortable(ioum) << 32) | (unsigned)(KTOP - 1 - i);
            if (key > best) best = key;
        }
        #pragma unroll
        for (int d = 16; d; d >>= 1) {
            u64 o = __shfl_xor_sync(0xffffffffu, best, d);
            if (o > best) best = o;
        }
        if (lane == 0) sbest[g] = best;
    }
    __syncthreads();

    // ---- stats epilogue (thread 0) ----
    if (tid == 0) {
        float sum_iou = 0.0f, sum_conf = 0.0f;
        int n_hit = 0, n_gt = 0;
        for (int g = 0; g < GG; g++) {
            int gm = gt_mask[b * GG + g];
            if (gm != 0) n_gt++;
            u64 key = sbest[g];
            float biou = sortable2f((unsigned)(key >> 32));
            int pidx = KTOP - 1 - (int)(key & 0xFFFFFFFFu);
            bool hit = (biou > 0.6f) && (gm != 0);
            if (hit) {
                n_hit++;
                sum_iou += biou;
                sum_conf += s_conf[pidx];
            }
        }
        float fh = (float)n_hit;
        float mean_iou  = __fdiv_rn(sum_iou, fmaxf(fh, 1.0f));
        float mean_conf = (n_hit > 0) ? __fdiv_rn(sum_conf, fmaxf(fh, 1.0f)) : 1.0f;
        float correct   = __fdiv_rn(fh, fmaxf((float)n_gt, 1.0f));

        float cc[NCLS];
        float sc[NSUP];
        for (int c = 0; c < NCLS; c++) cc[c] = 0.0f;
        for (int s = 0; s < NSUP; s++) sc[s] = 0.0f;
        for (int g = 0; g < GG; g++) {
            float gm = (gt_mask[b * GG + g] != 0) ? 1.0f : 0.0f;
            int c = gt_cls[b * GG + g];
            cc[c] += gm;
            sc[cat_to_super[c]] += gm;
        }
        float bc = cc[0]; int mfc = 0;
        for (int c = 1; c < NCLS; c++) if (cc[c] > bc) { bc = cc[c]; mfc = c; }
        float bs = sc[0]; int mfs = 0;
        for (int s = 1; s < NSUP; s++) if (sc[s] > bs) { bs = sc[s]; mfs = s; }

        float r0, r1, r2, r3, r4;
        if (n_gt == 0) {
            if (sh_npred == 0) { r0 = 1.0f; r1 = 1.0f; r2 = -1.0f; r3 = -1.0f; r4 = 1.0f; }
            else               { r0 = 0.0f; r1 = 1.0f; r2 = -2.0f; r3 = -2.0f; r4 = 0.0f; }
        } else {
            r0 = mean_iou; r1 = mean_conf; r2 = (float)mfc; r3 = (float)mfs; r4 = correct;
        }
        float* o = out + b * 5;
        o[0] = r0; o[1] = r1; o[2] = r2; o[3] = r3; o[4] = r4;
    }
}

// ---------------- launcher ----------------
extern "C" void kernel_launch(void* const* d_in, const int* in_sizes, int n_in,
                              void* d_out, int out_size) {
    const float* preds        = (const float*)d_in[0];
    const float* gt_boxes     = (const float*)d_in[1];
    const int*   gt_cls       = (const int*)d_in[2];
    const int*   gt_mask      = (const int*)d_in[3];
    const int*   cat_to_super = (const int*)d_in[4];
    float* out = (float*)d_out;

    (void)in_sizes; (void)n_in; (void)out_size;

    cudaFuncSetAttribute(fused_kernel, cudaFuncAttributeMaxDynamicSharedMemorySize,
                         FUSED_SMEM);

    decode_kernel<<<dim3((AA + 255) / 256, BB), 256>>>(preds);
    fused_kernel<<<BB, 1024, FUSED_SMEM>>>(preds, gt_boxes, gt_cls, gt_mask,
                                           cat_to_super, out);
}

// round 17
// speedup vs baseline: 1.4182x; 1.4182x over previous
#include <cuda_runtime.h>
#include <cstdint>

#define BB 32
#define AA 8400
#define AA_PAD 8448
#define NCLS 80
#define KTOP 1024
#define GG 32
#define NSUP 16
#define MAX_DET 300
#define KW (KTOP/32)
#define NBIN2 4098           // bin0 = conf==0, bins 1..4097 = (cbits>>12) - 0x3E800 + 1
#define NBIN2_PAD 4112
#define CAND 2048
#define CLS_BLKS 3

typedef unsigned long long u64;

// ---------------- static device scratch (zero-initialized; consumed-then-cleared) ----------------
__device__ u64      d_keys[BB * AA];
__device__ int      d_hist[BB * NBIN2_PAD];   // decode fills; select stages + re-zeroes
__device__ float    d_sel_conf[BB * KTOP];
__device__ int      d_sel_cls[BB * KTOP];
__device__ float4   d_sel_box[BB * KTOP];
__device__ float4   d_sel_sbox[BB * KTOP];
__device__ unsigned d_keep[BB * KW];          // nms ORs; match stages + re-zeroes

__device__ __forceinline__ unsigned f2sortable(float f) {
    unsigned b = __float_as_uint(f);
    return (b & 0x80000000u) ? ~b : (b | 0x80000000u);
}
__device__ __forceinline__ float sortable2f(unsigned s) {
    return __uint_as_float((s & 0x80000000u) ? (s ^ 0x80000000u) : ~s);
}

// ---------------- 1. decode: 4 threads per quad (20 classes each) + histogram ----------------
// key = (conf_bits << 32) | ((AA-1-a) << 7) | cls  (cls below index: tie order intact)
// Out-of-range threads clamp onto the last quad so EVERY lane executes the shfl
// collectives; only stores are guarded.
__global__ void decode_kernel(const float* __restrict__ preds) {
    __shared__ int hh[NBIN2];
    int b = blockIdx.y;
    int t = blockIdx.x * blockDim.x + threadIdx.x;   // 0 .. 8447
    for (int i = threadIdx.x; i < NBIN2; i += blockDim.x) hh[i] = 0;
    __syncthreads();

    bool live = (t < AA);
    int q = live ? (t >> 2) : (AA / 4 - 1);
    int k = t & 3;
    const float4* p4 = (const float4*)(preds + (size_t)b * 84 * AA);
    const int QW = AA / 4;                           // 2100

    float4 best = p4[(4 + k) * QW + q];
    int c0 = k, c1 = k, c2 = k, c3 = k;
    #pragma unroll 5
    for (int i = 1; i < 20; i++) {
        int c = k + 4 * i;
        float4 v = p4[(4 + c) * QW + q];
        if (v.x > best.x) { best.x = v.x; c0 = c; }
        if (v.y > best.y) { best.y = v.y; c1 = c; }
        if (v.z > best.z) { best.z = v.z; c2 = c; }
        if (v.w > best.w) { best.w = v.w; c3 = c; }
    }
    #pragma unroll
    for (int d = 1; d <= 2; d <<= 1) {
        float ox = __shfl_xor_sync(0xffffffffu, best.x, d);
        float oy = __shfl_xor_sync(0xffffffffu, best.y, d);
        float oz = __shfl_xor_sync(0xffffffffu, best.z, d);
        float ow = __shfl_xor_sync(0xffffffffu, best.w, d);
        int   o0 = __shfl_xor_sync(0xffffffffu, c0, d);
        int   o1 = __shfl_xor_sync(0xffffffffu, c1, d);
        int   o2 = __shfl_xor_sync(0xffffffffu, c2, d);
        int   o3 = __shfl_xor_sync(0xffffffffu, c3, d);
        if (ox > best.x || (ox == best.x && o0 < c0)) { best.x = ox; c0 = o0; }
        if (oy > best.y || (oy == best.y && o1 < c1)) { best.y = oy; c1 = o1; }
        if (oz > best.z || (oz == best.z && o2 < c2)) { best.z = oz; c2 = o2; }
        if (ow > best.w || (ow == best.w && o3 < c3)) { best.w = ow; c3 = o3; }
    }
    if (live) {
        float bv = (k == 0) ? best.x : (k == 1) ? best.y : (k == 2) ? best.z : best.w;
        int   cv = (k == 0) ? c0     : (k == 1) ? c1     : (k == 2) ? c2     : c3;
        int a = q * 4 + k;
        float conf = (bv > 0.25f) ? bv : 0.0f;
        unsigned cbits = __float_as_uint(conf);
        d_keys[b * AA + a] = ((u64)cbits << 32) | ((unsigned)(AA - 1 - a) << 7)
                           | (unsigned)cv;
        int bin = (conf == 0.0f) ? 0 : (int)(cbits >> 12) - 0x3E800 + 1;
        atomicAdd(&hh[bin], 1);
    }
    __syncthreads();
    for (int i = threadIdx.x; i < NBIN2; i += blockDim.x)
        if (hh[i]) atomicAdd(&d_hist[b * NBIN2_PAD + i], hh[i]);
}

// ---------------- 2. select: cutoff -> compact -> bitonic sort -> gather ----------------
#define BINS_PER_T 5
__global__ void __launch_bounds__(1024) select_kernel(const float* __restrict__ preds) {
    __shared__ u64 s_sort[CAND];
    __shared__ int s_hist[NBIN2];
    __shared__ int s_wsum[32], s_wafter[32];
    __shared__ int sh_cstar, sh_scnt;
    __shared__ u64 sh_thr;

    int b    = blockIdx.x;
    int tid  = threadIdx.x;                 // 1024
    int lane = tid & 31;
    int wid  = tid >> 5;
    const u64* keys = d_keys + (size_t)b * AA;

    // stage hist + re-zero global for next launch
    for (int i = tid; i < NBIN2; i += 1024) {
        s_hist[i] = d_hist[b * NBIN2_PAD + i];
        d_hist[b * NBIN2_PAD + i] = 0;
    }
    if (tid == 0) { sh_cstar = 1; sh_scnt = 0; }
    __syncthreads();

    // hierarchical suffix scan over bins 1..4097 -> cutoff bin (2 barriers)
    {
        int partial = 0;
        #pragma unroll
        for (int k = 0; k < BINS_PER_T; k++) {
            int c = tid * BINS_PER_T + k;
            if (c >= 1 && c < NBIN2) partial += s_hist[c];
        }
        int wsfx = partial;
        #pragma unroll
        for (int d = 1; d < 32; d <<= 1) {
            int v = __shfl_down_sync(0xffffffffu, wsfx, d);
            if (lane + d < 32) wsfx += v;
        }
        if (lane == 0) s_wsum[wid] = wsfx;
        __syncthreads();
        if (wid == 0) {
            int wt = s_wsum[lane];
            int wsf = wt;
            #pragma unroll
            for (int d = 1; d < 32; d <<= 1) {
                int v = __shfl_down_sync(0xffffffffu, wsf, d);
                if (lane + d < 32) wsf += v;
            }
            s_wafter[lane] = wsf - wt;
        }
        __syncthreads();
        int sfx = wsfx + s_wafter[wid];
        int nxt = sfx - partial;
        if (sfx >= KTOP && nxt < KTOP) {
            int cum = nxt, cstar = 1;
            for (int c = min(tid * BINS_PER_T + BINS_PER_T - 1, NBIN2 - 1);
                 c >= tid * BINS_PER_T; c--) {
                if (c < 1) break;
                cum += s_hist[c];
                if (cum >= KTOP) { cstar = c; break; }
            }
            sh_cstar = cstar;
        }
    }
    __syncthreads();
    if (tid == 0) {
        unsigned thrhi = ((unsigned)(sh_cstar - 1 + 0x3E800)) << 12;
        sh_thr = (u64)thrhi << 32;
    }
    for (int i = tid; i < CAND; i += 1024) s_sort[i] = 0ull;
    __syncthreads();

    // compact candidates >= thr (warp-aggregated)
    {
        u64 thr = sh_thr;
        for (int base = 0; base < AA_PAD; base += 1024) {
            int i = base + tid;
            u64 k = (i < AA) ? keys[i] : 0ull;
            bool pred = (i < AA) && (k >= thr);
            unsigned ball = __ballot_sync(0xffffffffu, pred);
            int cnt = __popc(ball);
            int pos0 = 0;
            if (lane == 0 && cnt) pos0 = atomicAdd(&sh_scnt, cnt);
            pos0 = __shfl_sync(0xffffffffu, pos0, 0);
            if (pred) {
                int pos = pos0 + __popc(ball & ((1u << lane) - 1));
                if (pos < CAND) s_sort[pos] = k;
            }
        }
    }
    __syncthreads();

    // descending bitonic sort of 2048 unique keys
    for (int k = 2; k <= CAND; k <<= 1) {
        for (int j = k >> 1; j > 0; j >>= 1) {
            #pragma unroll
            for (int rep = 0; rep < CAND / 1024; rep++) {
                int t = rep * 1024 + tid;
                int ixj = t ^ j;
                if (ixj > t) {
                    u64 x = s_sort[t], y = s_sort[ixj];
                    bool up = ((t & k) == 0);
                    if (up ? (x < y) : (x > y)) { s_sort[t] = y; s_sort[ixj] = x; }
                }
            }
            __syncthreads();
        }
    }

    // gather: rank tid = s_sort[tid]
    {
        u64 key = s_sort[tid];
        float conf = __uint_as_float((unsigned)(key >> 32));
        int a = AA - 1 - (int)((key >> 7) & 0x3FFF);
        int cls = (int)(key & 0x7F);
        const float* p = preds + (size_t)b * 84 * AA;
        float cx = p[0 * AA + a], cy = p[1 * AA + a];
        float w  = p[2 * AA + a], h  = p[3 * AA + a];
        float x1 = cx - 0.5f * w, y1 = cy - 0.5f * h;
        float x2 = cx + 0.5f * w, y2 = cy + 0.5f * h;
        float sh = (float)cls * 7680.0f;
        int o = b * KTOP + tid;
        d_sel_conf[o] = conf;
        d_sel_cls[o]  = cls;
        d_sel_box[o]  = make_float4(x1, y1, x2, y2);
        d_sel_sbox[o] = make_float4(x1 + sh, y1 + sh, x2 + sh, y2 + sh);
    }
}

// ---------------- 3. NMS: one class per WARP, grid (BB, 3), boxes in smem ----------------
// Cross-class IOU is exactly zero (class shift >= 7680 vs coords <= ~800), so greedy
// NMS decomposes per class. Chains read staged smem (29-cyc LDS vs 234-cyc L2).
__global__ void __launch_bounds__(1024) nms_kernel() {
    __shared__ float4   s_sbox[KTOP];        // 16 KB
    __shared__ unsigned s_cmask[NCLS * 32];  // 10 KB
    int b = blockIdx.x;
    int tid = threadIdx.x;                   // 1024
    int lane = tid & 31;
    int wid  = tid >> 5;

    for (int i = tid; i < NCLS * 32; i += 1024) s_cmask[i] = 0;
    __syncthreads();
    {
        s_sbox[tid] = d_sel_sbox[b * KTOP + tid];
        float conf = d_sel_conf[b * KTOP + tid];
        int cls    = d_sel_cls[b * KTOP + tid];
        if (conf > 0.0f)
            atomicOr(&s_cmask[cls * 32 + (tid >> 5)], 1u << (tid & 31));
    }
    __syncthreads();

    int c = blockIdx.y * 32 + wid;
    if (c >= NCLS) return;

    unsigned rem_w = s_cmask[c * 32 + lane];
    unsigned keep_bits = 0;
    while (true) {
        unsigned anyb = __ballot_sync(0xffffffffu, rem_w != 0);
        if (!anyb) break;
        int src = __ffs(anyb) - 1;
        unsigned w0 = __shfl_sync(0xffffffffu, rem_w, src);
        int jb0 = __ffs(w0) - 1;
        int r = src * 32 + jb0;              // lowest remaining rank: KEPT
        if (lane == src) {
            rem_w &= ~(1u << jb0);
            keep_bits |= (1u << jb0);
        }
        float4 bi = s_sbox[r];               // broadcast LDS
        float ai = (bi.z - bi.x) * (bi.w - bi.y);
        unsigned w = rem_w;
        while (w) {
            int jb = __ffs(w) - 1; w &= w - 1;
            float4 bj = s_sbox[lane * 32 + jb];
            float lx = fmaxf(bi.x, bj.x), ly = fmaxf(bi.y, bj.y);
            float rx = fminf(bi.z, bj.z), ry = fminf(bi.w, bj.w);
            float iw = fmaxf(rx - lx, 0.0f), ih = fmaxf(ry - ly, 0.0f);
            float inter = iw * ih;
            float aj = (bj.z - bj.x) * (bj.w - bj.y);
            float denom = ai + aj - inter + 1e-9f;
            float iou = __fdiv_rn(inter, denom);
            if (iou > 0.45f) rem_w &= ~(1u << jb);
        }
    }
    if (keep_bits) atomicOr(&d_keep[b * KW + lane], keep_bits);
}

// ---------------- 4. match: trim -> pv -> warp-per-GT -> stats ----------------
__global__ void __launch_bounds__(1024) match_kernel(
    const float* __restrict__ gt_boxes,
    const int*   __restrict__ gt_cls,
    const int*   __restrict__ gt_mask,
    const int*   __restrict__ cat_to_super,
    float* __restrict__ out)
{
    __shared__ float4 s_box[KTOP];           // 16 KB
    __shared__ float  s_conf[KTOP];          //  4 KB
    __shared__ int    s_cls[KTOP];           //  4 KB
    __shared__ float4 sgt[GG];
    __shared__ int    sgc[GG];
    __shared__ u64    sbest[GG];
    __shared__ unsigned s_keepw[KW];
    __shared__ unsigned s_pv[32];
    __shared__ int sh_npred;

    int b = blockIdx.x;
    int tid = threadIdx.x;                   // 1024
    int lane = tid & 31;
    int wid  = tid >> 5;

    s_box[tid]  = d_sel_box[b * KTOP + tid];
    s_conf[tid] = d_sel_conf[b * KTOP + tid];
    s_cls[tid]  = d_sel_cls[b * KTOP + tid];
    if (tid < GG) {
        const float* gb = gt_boxes + (size_t)(b * GG + tid) * 4;
        sgt[tid] = make_float4(gb[0], gb[1], gb[2], gb[3]);
        sgc[tid] = gt_cls[b * GG + tid];
        sbest[tid] = 0ull;
    }
    if (tid == 0) sh_npred = 0;

    // trim keep bits to MAX_DET in kept-rank order (warp 0); re-zero global
    if (tid < 32) {
        unsigned keep_local = d_keep[b * KW + lane];
        d_keep[b * KW + lane] = 0;           // cleared for next launch
        int myc = __popc(keep_local);
        int pre = myc;
        #pragma unroll
        for (int d = 1; d < 32; d <<= 1) {
            int v = __shfl_up_sync(0xffffffffu, pre, d);
            if (lane >= d) pre += v;
        }
        pre -= myc;
        unsigned kw2 = 0, tmp = keep_local;
        while (tmp) {
            int p = __ffs(tmp) - 1; tmp &= tmp - 1;
            int rank = pre + __popc(keep_local & ((1u << p) - 1));
            if (rank < MAX_DET) kw2 |= (1u << p);
        }
        s_keepw[lane] = kw2;
    }
    __syncthreads();

    // pv bits + npred
    {
        bool kb = (s_keepw[tid >> 5] >> (tid & 31)) & 1u;
        bool pv = kb && (s_conf[tid] > 0.5f);
        unsigned ball = __ballot_sync(0xffffffffu, pv);
        if (lane == 0) {
            s_pv[wid] = ball;
            atomicAdd(&sh_npred, __popc(ball));
        }
    }
    __syncthreads();

    // warp g owns GT g; lanes stride preds; ONE reduce per warp
    {
        int g = wid;
        float4 gb = sgt[g];
        int gc = sgc[g];
        float ag = (gb.z - gb.x) * (gb.w - gb.y);
        u64 best = 0ull;
        #pragma unroll 4
        for (int i = lane; i < KTOP; i += 32) {
            float4 bx = s_box[i];
            float lx = fmaxf(bx.x, gb.x), ly = fmaxf(bx.y, gb.y);
            float rx = fminf(bx.z, gb.z), ry = fminf(bx.w, gb.w);
            float iw = fmaxf(rx - lx, 0.0f), ih = fmaxf(ry - ly, 0.0f);
            float inter = iw * ih;
            float ap = (bx.z - bx.x) * (bx.w - bx.y);
            float iou = __fdiv_rn(inter, ap + ag - inter + 1e-9f);
            bool pv = (s_pv[i >> 5] >> (i & 31)) & 1u;
            float ioum = (pv && s_cls[i] == gc) ? iou : -1.0f;
            u64 key = ((u64)f2sortable(ioum) << 32) | (unsigned)(KTOP - 1 - i);
            if (key > best) best = key;
        }
        #pragma unroll
        for (int d = 16; d; d >>= 1) {
            u64 o = __shfl_xor_sync(0xffffffffu, best, d);
            if (o > best) best = o;
        }
        if (lane == 0) sbest[g] = best;
    }
    __syncthreads();

    // stats epilogue (thread 0)
    if (tid == 0) {
        float sum_iou = 0.0f, sum_conf = 0.0f;
        int n_hit = 0, n_gt = 0;
        for (int g = 0; g < GG; g++) {
            int gm = gt_mask[b * GG + g];
            if (gm != 0) n_gt++;
            u64 key = sbest[g];
            float biou = sortable2f((unsigned)(key >> 32));
            int pidx = KTOP - 1 - (int)(key & 0xFFFFFFFFu);
            bool hit = (biou > 0.6f) && (gm != 0);
            if (hit) {
                n_hit++;
                sum_iou += biou;
                sum_conf += s_conf[pidx];
            }
        }
        float fh = (float)n_hit;
        float mean_iou  = __fdiv_rn(sum_iou, fmaxf(fh, 1.0f));
        float mean_conf = (n_hit > 0) ? __fdiv_rn(sum_conf, fmaxf(fh, 1.0f)) : 1.0f;
        float correct   = __fdiv_rn(fh, fmaxf((float)n_gt, 1.0f));

        float cc[NCLS];
        float sc[NSUP];
        for (int c = 0; c < NCLS; c++) cc[c] = 0.0f;
        for (int s = 0; s < NSUP; s++) sc[s] = 0.0f;
        for (int g = 0; g < GG; g++) {
            float gm = (gt_mask[b * GG + g] != 0) ? 1.0f : 0.0f;
            int c = gt_cls[b * GG + g];
            cc[c] += gm;
            sc[cat_to_super[c]] += gm;
        }
        float bc = cc[0]; int mfc = 0;
        for (int c = 1; c < NCLS; c++) if (cc[c] > bc) { bc = cc[c]; mfc = c; }
        float bs = sc[0]; int mfs = 0;
        for (int s = 1; s < NSUP; s++) if (sc[s] > bs) { bs = sc[s]; mfs = s; }

        float r0, r1, r2, r3, r4;
        if (n_gt == 0) {
            if (sh_npred == 0) { r0 = 1.0f; r1 = 1.0f; r2 = -1.0f; r3 = -1.0f; r4 = 1.0f; }
            else               { r0 = 0.0f; r1 = 1.0f; r2 = -2.0f; r3 = -2.0f; r4 = 0.0f; }
        } else {
            r0 = mean_iou; r1 = mean_conf; r2 = (float)mfc; r3 = (float)mfs; r4 = correct;
        }
        float* o = out + b * 5;
        o[0] = r0; o[1] = r1; o[2] = r2; o[3] = r3; o[4] = r4;
    }
}

// ---------------- launcher ----------------
extern "C" void kernel_launch(void* const* d_in, const int* in_sizes, int n_in,
                              void* d_out, int out_size) {
    const float* preds        = (const float*)d_in[0];
    const float* gt_boxes     = (const float*)d_in[1];
    const int*   gt_cls       = (const int*)d_in[2];
    const int*   gt_mask      = (const int*)d_in[3];
    const int*   cat_to_super = (const int*)d_in[4];
    float* out = (float*)d_out;

    (void)in_sizes; (void)n_in; (void)out_size;

    decode_kernel<<<dim3((AA + 255) / 256, BB), 256>>>(preds);
    select_kernel<<<BB, 1024>>>(preds);
    nms_kernel<<<dim3(BB, CLS_BLKS), 1024>>>();
    match_kernel<<<BB, 1024>>>(gt_boxes, gt_cls, gt_mask, cat_to_super, out);
}